// round 16
// baseline (speedup 1.0000x reference)
#include <cuda_runtime.h>
#include <cuda_bf16.h>
#include <cstdint>

#define BB 4
#define C 128
#define H 128
#define W 128
#define HW (H*W)

typedef unsigned long long ull;

// ------------------------- device scratch (no allocs) -----------------------
__device__ float          g_U[(size_t)BB*C*HW];  // u' = x.M + v2, layout [b][oc][px]
__device__ unsigned short g_Mhi[C*C];            // M^T hi, plain bf16 [oc][ic]
__device__ unsigned short g_Mlo[C*C];            // M^T lo
__device__ float          g_v1[C];
__device__ float          g_v2[C];
__device__ float          g_gamma[1];

__device__ __forceinline__ uint32_t smem_u32(const void* p){
    uint32_t a;
    asm("{ .reg .u64 t; cvta.to.shared.u64 t, %1; cvt.u32.u64 %0, t; }" : "=r"(a) : "l"(p));
    return a;
}
__device__ __forceinline__ void ldm_x4(uint32_t addr, uint32_t& r0, uint32_t& r1,
                                       uint32_t& r2, uint32_t& r3){
    asm volatile("ldmatrix.sync.aligned.m8n8.x4.shared.b16 {%0,%1,%2,%3}, [%4];"
        : "=r"(r0), "=r"(r1), "=r"(r2), "=r"(r3) : "r"(addr));
}
__device__ __forceinline__ void mma_bf16(float* d, const uint32_t* a, const uint32_t* b){
    asm volatile("mma.sync.aligned.m16n8k16.row.col.f32.bf16.bf16.f32 "
        "{%0,%1,%2,%3}, {%4,%5,%6,%7}, {%8,%9}, {%0,%1,%2,%3};"
        : "+f"(d[0]), "+f"(d[1]), "+f"(d[2]), "+f"(d[3])
        : "r"(a[0]), "r"(a[1]), "r"(a[2]), "r"(a[3]), "r"(b[0]), "r"(b[1]));
}
__device__ __forceinline__ void split_bf16(float v, unsigned short& h, unsigned short& l){
    __nv_bfloat16 bh = __float2bfloat16(v);
    float r = v - __bfloat162float(bh);
    __nv_bfloat16 bl = __float2bfloat16(r);
    h = __bfloat16_as_ushort(bh);
    l = __bfloat16_as_ushort(bl);
}

// ---------------------------------------------------------------------------
// precomp v2: split-k (4 ways, 512 threads) + smem reduction.
// M^T[oc][ic] = sum_t qw[t][ic]*kw[t][oc] (bf16 hi/lo), v1, v2, gamma.
// ---------------------------------------------------------------------------
__global__ __launch_bounds__(512) void precomp_kernel(const float* __restrict__ qw,
                                                      const float* __restrict__ qb,
                                                      const float* __restrict__ kw,
                                                      const float* __restrict__ kb){
    __shared__ float col[C];
    __shared__ float part[4][C];
    const int ci = blockIdx.x;
    const int t  = threadIdx.x;
    const int ic = t & 127;
    const int ks = t >> 7;           // 0..3
    const int kbase = ks * 32;

    if (ci < 128){
        const int oc = ci;
        if (t < 128) col[t] = __ldg(kw + t*C + oc);
        __syncthreads();
        float a0 = 0.f, a1 = 0.f;
        #pragma unroll 8
        for (int j = 0; j < 32; j += 2){
            a0 = fmaf(__ldg(qw + (kbase+j+0)*C + ic), col[kbase+j+0], a0);
            a1 = fmaf(__ldg(qw + (kbase+j+1)*C + ic), col[kbase+j+1], a1);
        }
        part[ks][ic] = a0 + a1;
        __syncthreads();
        if (ks == 0){
            float acc = (part[0][ic] + part[1][ic]) + (part[2][ic] + part[3][ic]);
            unsigned short h, l;
            split_bf16(acc, h, l);
            g_Mhi[oc*C + ic] = h;
            g_Mlo[oc*C + ic] = l;
        }
    } else if (ci == 128){
        if (t < 128) col[t] = __ldg(kb + t);
        __syncthreads();
        float a0 = 0.f, a1 = 0.f;
        #pragma unroll 8
        for (int j = 0; j < 32; j += 2){
            a0 = fmaf(__ldg(qw + (kbase+j+0)*C + ic), col[kbase+j+0], a0);
            a1 = fmaf(__ldg(qw + (kbase+j+1)*C + ic), col[kbase+j+1], a1);
        }
        part[ks][ic] = a0 + a1;
        __syncthreads();
        if (ks == 0)
            g_v1[ic] = (part[0][ic] + part[1][ic]) + (part[2][ic] + part[3][ic]);
    } else {
        if (t < 128) col[t] = __ldg(qb + t);
        __syncthreads();
        float a0 = 0.f, a1 = 0.f;
        #pragma unroll 8
        for (int j = 0; j < 32; j += 2){
            a0 = fmaf(col[kbase+j+0], __ldg(kw + (kbase+j+0)*C + ic), a0);
            a1 = fmaf(col[kbase+j+1], __ldg(kw + (kbase+j+1)*C + ic), a1);
        }
        part[ks][ic] = a0 + a1;
        __syncthreads();
        if (ks == 0)
            g_v2[ic] = (part[0][ic] + part[1][ic]) + (part[2][ic] + part[3][ic]);
        // gamma: warp 0, parallel reduce
        if (t < 32){
            float g = 0.f;
            #pragma unroll
            for (int k = t; k < C; k += 32)
                g = fmaf(__ldg(qb + k), __ldg(kb + k), g);
            #pragma unroll
            for (int o = 16; o > 0; o >>= 1)
                g += __shfl_xor_sync(0xFFFFFFFF, g, o);
            if (t == 0) g_gamma[0] = g;
        }
    }
}

// ---------------------------------------------------------------------------
// proj: u'[b][oc][px] = sum_ic x[ic][px]*M[ic][oc] + v2[oc]
// mma.sync bf16 3-term compensated GEMM. 512 threads, ks-outer loop.
// (unchanged — near its HMMA throughput floor)
// ---------------------------------------------------------------------------
#define A_STRIDE 272
#define TILE_BYTES (128 * A_STRIDE)
#define AH_OFF 0
#define AL_OFF (TILE_BYTES)
#define BH_OFF (2*TILE_BYTES)
#define BL_OFF (3*TILE_BYTES)
#define PROJ_SMEM (4*TILE_BYTES)

__global__ __launch_bounds__(512) void proj_kernel(const float* __restrict__ feat){
    extern __shared__ char sm[];
    const uint32_t smb = smem_u32(sm);
    const int tid  = threadIdx.x;
    const int lane = tid & 31;
    const int wid  = tid >> 5;
    const int b    = blockIdx.y;
    const int px0  = blockIdx.x * 128;

    {
        const float4* sh = (const float4*)g_Mhi;
        const float4* sl = (const float4*)g_Mlo;
        for (int e = tid; e < 2048; e += 512){
            int row = e >> 4, seg = e & 15;
            *(float4*)(sm + BH_OFF + row*A_STRIDE + seg*16) = sh[row*16 + seg];
            *(float4*)(sm + BL_OFF + row*A_STRIDE + seg*16) = sl[row*16 + seg];
        }
    }
    {
        const int px  = tid & 127;
        const int ic0 = (tid >> 7) * 32;
        const float* fp = feat + (size_t)(b*C + ic0)*HW + px0 + px;
        char* ah = sm + AH_OFF + px*A_STRIDE + ic0*2;
        char* al = sm + AL_OFF + px*A_STRIDE + ic0*2;
        #pragma unroll
        for (int g = 0; g < 8; g++){
            float v0 = fp[(size_t)(g*4+0)*HW];
            float v1 = fp[(size_t)(g*4+1)*HW];
            float v2 = fp[(size_t)(g*4+2)*HW];
            float v3 = fp[(size_t)(g*4+3)*HW];
            unsigned short h0,h1,h2,h3,l0,l1,l2,l3;
            split_bf16(v0,h0,l0); split_bf16(v1,h1,l1);
            split_bf16(v2,h2,l2); split_bf16(v3,h3,l3);
            *(ull*)(ah + g*8) = (ull)h0 | ((ull)h1<<16) | ((ull)h2<<32) | ((ull)h3<<48);
            *(ull*)(al + g*8) = (ull)l0 | ((ull)l1<<16) | ((ull)l2<<32) | ((ull)l3<<48);
        }
    }
    __syncthreads();

    const int wy = wid >> 1;
    const int wx = wid & 1;
    const int m_base = wy * 16;
    const int n_base = wx * 64;

    float d[8][4];
    #pragma unroll
    for (int j = 0; j < 8; j++)
        #pragma unroll
        for (int k = 0; k < 4; k++) d[j][k] = 0.f;

    const int a_sub = lane >> 3;
    const int a_row_off = (a_sub & 1)*8 + (lane & 7);
    const int a_col_off = (a_sub >> 1)*8;
    const int b_row_off = (a_sub >> 1)*8 + (lane & 7);
    const int b_col_off = (a_sub & 1)*8;

    const uint32_t a_addr_h = smb + AH_OFF + (m_base + a_row_off)*A_STRIDE + a_col_off*2;
    const uint32_t a_addr_l = smb + AL_OFF + (m_base + a_row_off)*A_STRIDE + a_col_off*2;
    const uint32_t b_addr_h = smb + BH_OFF + (n_base + b_row_off)*A_STRIDE + b_col_off*2;
    const uint32_t b_addr_l = smb + BL_OFF + (n_base + b_row_off)*A_STRIDE + b_col_off*2;

    #pragma unroll
    for (int ks = 0; ks < 8; ks++){
        const int k0 = ks * 32;

        uint32_t ah[4], al[4];
        ldm_x4(a_addr_h + k0, ah[0], ah[1], ah[2], ah[3]);
        ldm_x4(a_addr_l + k0, al[0], al[1], al[2], al[3]);

        uint32_t bh[8][2], bl[8][2];
        #pragma unroll
        for (int nb2 = 0; nb2 < 4; nb2++){
            uint32_t r0, r1, r2, r3;
            ldm_x4(b_addr_h + nb2*16*A_STRIDE + k0, r0, r1, r2, r3);
            bh[nb2*2][0] = r0; bh[nb2*2][1] = r1;
            bh[nb2*2+1][0] = r2; bh[nb2*2+1][1] = r3;
            ldm_x4(b_addr_l + nb2*16*A_STRIDE + k0, r0, r1, r2, r3);
            bl[nb2*2][0] = r0; bl[nb2*2][1] = r1;
            bl[nb2*2+1][0] = r2; bl[nb2*2+1][1] = r3;
        }
        #pragma unroll
        for (int nb = 0; nb < 8; nb++){
            mma_bf16(d[nb], ah, bh[nb]);
            mma_bf16(d[nb], ah, bl[nb]);
            mma_bf16(d[nb], al, bh[nb]);
        }
    }

    {
        const int gid = lane >> 2;
        const int tq  = lane & 3;
        float* ub = g_U + (size_t)b*C*HW + px0;
        const int px = m_base + gid;
        #pragma unroll
        for (int nb = 0; nb < 8; nb++){
            const int oc = n_base + nb*8 + tq*2;
            const float v2a = __ldg(g_v2 + oc);
            const float v2b = __ldg(g_v2 + oc + 1);
            float* r0 = ub + (size_t)oc * HW;
            float* r1 = ub + (size_t)(oc+1) * HW;
            r0[px]     = d[nb][0] + v2a;
            r1[px]     = d[nb][1] + v2b;
            r0[px + 8] = d[nb][2] + v2a;
            r1[px + 8] = d[nb][3] + v2b;
        }
    }
}

// ---------------------------------------------------------------------------
// attn v3: double-buffered halo staging. One CTA per (batch, row).
// 256 threads = 2 channel-halves x 128 px. One __syncthreads per iteration;
// stage(i+1) LDGs issue before compute(i), hiding gmem latency under LDS work.
// ---------------------------------------------------------------------------
#define SKS 136
#define SK_BUF_FLOATS (16*3*SKS)               // 6528 floats = 26112 B
#define ATTN_SK0   0
#define ATTN_SK1   (SK_BUF_FLOATS*4)
#define ATTN_SV1   (2*SK_BUF_FLOATS*4)         // 52224
#define ATTN_SRED  (ATTN_SV1 + 512)            // 52736
#define ATTN_SMEM  (ATTN_SRED + 128*11*4)      // 58368

__global__ __launch_bounds__(256) void attn_kernel(const float* __restrict__ feat,
                                                   const float* __restrict__ flow,
                                                   float* __restrict__ out){
    extern __shared__ char sma[];
    float* sKb[2] = { (float*)(sma + ATTN_SK0), (float*)(sma + ATTN_SK1) };
    float* sV1    = (float*)(sma + ATTN_SV1);
    float* sRed   = (float*)(sma + ATTN_SRED);

    const int tid  = threadIdx.x;
    const int lane = tid & 31;
    const int wid  = tid >> 5;
    const int b    = blockIdx.y;
    const int row  = blockIdx.x;
    const int x    = tid & 127;
    const int half = tid >> 7;

    if (tid < C) sV1[tid] = g_v1[tid];
    if (tid >= 128 && tid < 224){
        int idx = tid - 128;           // 0..95: 2 buffers x 48 rows
        int bufi = idx / 48;
        int rem  = idx - bufi*48;
        float* p = sKb[bufi] + rem*SKS;
        p[3]   = 0.f;
        p[132] = 0.f;
    }

    const float* fb = feat + (size_t)b*C*HW;
    const float* ub = g_U + (size_t)b*C*HW + row*W + x;

    float s[9];
    #pragma unroll
    for (int n = 0; n < 9; n++) s[n] = 0.f;
    float a = 0.f;

    // stage block 0
    {
        #pragma unroll
        for (int t = wid; t < 48; t += 8){
            const int c16 = t / 3;
            const int r   = t - c16*3;
            const int ch  = (c16 < 8) ? c16 : (64 + (c16 - 8));
            const int gy  = row - 1 + r;
            float* dst = sKb[0] + (c16*3 + r)*SKS + 4;
            if ((unsigned)gy < (unsigned)H)
                *(float4*)(dst + 4*lane) = __ldg((const float4*)(fb + (size_t)ch*HW + gy*W) + lane);
            else
                *(float4*)(dst + 4*lane) = make_float4(0.f, 0.f, 0.f, 0.f);
        }
    }
    __syncthreads();

    for (int i = 0; i < 8; i++){
        // stage block i+1 into the other buffer (overlaps with compute below)
        if (i < 7){
            float* buf = sKb[(i+1) & 1];
            #pragma unroll
            for (int t = wid; t < 48; t += 8){
                const int c16 = t / 3;
                const int r   = t - c16*3;
                const int ch  = (c16 < 8) ? ((i+1)*8 + c16) : (64 + (i+1)*8 + (c16 - 8));
                const int gy  = row - 1 + r;
                float* dst = buf + (c16*3 + r)*SKS + 4;
                if ((unsigned)gy < (unsigned)H)
                    *(float4*)(dst + 4*lane) = __ldg((const float4*)(fb + (size_t)ch*HW + gy*W) + lane);
                else
                    *(float4*)(dst + 4*lane) = make_float4(0.f, 0.f, 0.f, 0.f);
            }
        }

        // compute on block i
        const float* buf = sKb[i & 1];
        const int cb16 = half * 8;
        const int chb  = half * 64 + i*8;
        #pragma unroll
        for (int cc = 0; cc < 8; cc++){
            const float* kr = buf + (cb16 + cc)*3*SKS;
            float uv = ub[(size_t)(chb + cc)*HW];
            float center = kr[SKS + 4 + x];       // row 1, dx=1
            a = fmaf(sV1[chb + cc], center, a);
            #pragma unroll
            for (int dy = 0; dy < 3; dy++){
                s[dy*3+0] = fmaf(uv, kr[dy*SKS + 3 + x], s[dy*3+0]);
                s[dy*3+1] = fmaf(uv, (dy == 1) ? center : kr[dy*SKS + 4 + x], s[dy*3+1]);
                s[dy*3+2] = fmaf(uv, kr[dy*SKS + 5 + x], s[dy*3+2]);
            }
        }
        __syncthreads();
    }

    // reduce the two channel-halves
    if (half == 1){
        float* rp = sRed + x*11;
        #pragma unroll
        for (int n = 0; n < 9; n++) rp[n] = s[n];
        rp[9] = a;
    }
    __syncthreads();

    if (half == 0){
        const float* rp = sRed + x*11;
        #pragma unroll
        for (int n = 0; n < 9; n++) s[n] += rp[n];
        a += rp[9];

        const float alpha = a + g_gamma[0];
        const float INV = 0.08838834764831843f;   // 1/sqrt(128)

        float sc[9];
        #pragma unroll
        for (int dy = 0; dy < 3; dy++)
            #pragma unroll
            for (int dx = 0; dx < 3; dx++){
                int n = dy*3+dx;
                bool inb = ((unsigned)(row+dy-1) < (unsigned)H) &&
                           ((unsigned)(x+dx-1) < (unsigned)W);
                sc[n] = inb ? (s[n] + alpha) * INV : 0.f;
            }

        float m = sc[0];
        #pragma unroll
        for (int n = 1; n < 9; n++) m = fmaxf(m, sc[n]);
        float es[9], sum = 0.f;
        #pragma unroll
        for (int n = 0; n < 9; n++){ es[n] = __expf(sc[n] - m); sum += es[n]; }
        const float isum = 1.f / sum;

        const float* fl0 = flow + (size_t)(b*2)*HW;
        const float* fl1 = fl0 + HW;
        float f0 = 0.f, f1 = 0.f;
        #pragma unroll
        for (int dy = 0; dy < 3; dy++)
            #pragma unroll
            for (int dx = 0; dx < 3; dx++){
                int n = dy*3+dx;
                int gy = row + dy - 1, gx = x + dx - 1;
                if ((unsigned)gy < (unsigned)H && (unsigned)gx < (unsigned)W){
                    int pn = gy*W + gx;
                    float pr = es[n] * isum;
                    f0 = fmaf(pr, fl0[pn], f0);
                    f1 = fmaf(pr, fl1[pn], f1);
                }
            }
        out[(size_t)(b*2)*HW + row*W + x]   = f0;
        out[(size_t)(b*2+1)*HW + row*W + x] = f1;
    }
}

extern "C" void kernel_launch(void* const* d_in, const int* in_sizes, int n_in,
                              void* d_out, int out_size){
    const float* feature0 = (const float*)d_in[0];
    const float* flow     = (const float*)d_in[1];
    const float* q_w      = (const float*)d_in[2];
    const float* q_b      = (const float*)d_in[3];
    const float* k_w      = (const float*)d_in[4];
    const float* k_b      = (const float*)d_in[5];
    float* out = (float*)d_out;
    (void)in_sizes; (void)n_in; (void)out_size;

    precomp_kernel<<<130, 512>>>(q_w, q_b, k_w, k_b);

    cudaFuncSetAttribute(proj_kernel, cudaFuncAttributeMaxDynamicSharedMemorySize, PROJ_SMEM);
    proj_kernel<<<dim3(HW/128, BB), 512, PROJ_SMEM>>>(feature0);

    cudaFuncSetAttribute(attn_kernel, cudaFuncAttributeMaxDynamicSharedMemorySize, ATTN_SMEM);
    attn_kernel<<<dim3(H, BB), 256, ATTN_SMEM>>>(feature0, flow, out);
}

// round 17
// speedup vs baseline: 1.3176x; 1.3176x over previous
#include <cuda_runtime.h>
#include <cuda_bf16.h>
#include <cstdint>

#define BB 4
#define C 128
#define H 128
#define W 128
#define HW (H*W)

typedef unsigned long long ull;

// ------------------------- device scratch (no allocs) -----------------------
__device__ float          g_U[(size_t)BB*C*HW];  // u' = x.M + v2, layout [b][oc][px]
__device__ unsigned short g_Mhi[C*C];            // M^T hi, plain bf16 [oc][ic]
__device__ unsigned short g_Mlo[C*C];            // M^T lo
__device__ float          g_v1[C];
__device__ float          g_v2[C];
__device__ float          g_gamma[1];

__device__ __forceinline__ uint32_t smem_u32(const void* p){
    uint32_t a;
    asm("{ .reg .u64 t; cvta.to.shared.u64 t, %1; cvt.u32.u64 %0, t; }" : "=r"(a) : "l"(p));
    return a;
}
__device__ __forceinline__ void ldm_x4(uint32_t addr, uint32_t& r0, uint32_t& r1,
                                       uint32_t& r2, uint32_t& r3){
    asm volatile("ldmatrix.sync.aligned.m8n8.x4.shared.b16 {%0,%1,%2,%3}, [%4];"
        : "=r"(r0), "=r"(r1), "=r"(r2), "=r"(r3) : "r"(addr));
}
__device__ __forceinline__ void mma_bf16(float* d, const uint32_t* a, const uint32_t* b){
    asm volatile("mma.sync.aligned.m16n8k16.row.col.f32.bf16.bf16.f32 "
        "{%0,%1,%2,%3}, {%4,%5,%6,%7}, {%8,%9}, {%0,%1,%2,%3};"
        : "+f"(d[0]), "+f"(d[1]), "+f"(d[2]), "+f"(d[3])
        : "r"(a[0]), "r"(a[1]), "r"(a[2]), "r"(a[3]), "r"(b[0]), "r"(b[1]));
}
__device__ __forceinline__ void split_bf16(float v, unsigned short& h, unsigned short& l){
    __nv_bfloat16 bh = __float2bfloat16(v);
    float r = v - __bfloat162float(bh);
    __nv_bfloat16 bl = __float2bfloat16(r);
    h = __bfloat16_as_ushort(bh);
    l = __bfloat16_as_ushort(bl);
}

// ---------------------------------------------------------------------------
// precomp v2 (kept from R16 — measured 6.7us): split-k 4 ways, 512 threads.
// ---------------------------------------------------------------------------
__global__ __launch_bounds__(512) void precomp_kernel(const float* __restrict__ qw,
                                                      const float* __restrict__ qb,
                                                      const float* __restrict__ kw,
                                                      const float* __restrict__ kb){
    __shared__ float col[C];
    __shared__ float part[4][C];
    const int ci = blockIdx.x;
    const int t  = threadIdx.x;
    const int ic = t & 127;
    const int ks = t >> 7;
    const int kbase = ks * 32;

    if (ci < 128){
        const int oc = ci;
        if (t < 128) col[t] = __ldg(kw + t*C + oc);
        __syncthreads();
        float a0 = 0.f, a1 = 0.f;
        #pragma unroll 8
        for (int j = 0; j < 32; j += 2){
            a0 = fmaf(__ldg(qw + (kbase+j+0)*C + ic), col[kbase+j+0], a0);
            a1 = fmaf(__ldg(qw + (kbase+j+1)*C + ic), col[kbase+j+1], a1);
        }
        part[ks][ic] = a0 + a1;
        __syncthreads();
        if (ks == 0){
            float acc = (part[0][ic] + part[1][ic]) + (part[2][ic] + part[3][ic]);
            unsigned short h, l;
            split_bf16(acc, h, l);
            g_Mhi[oc*C + ic] = h;
            g_Mlo[oc*C + ic] = l;
        }
    } else if (ci == 128){
        if (t < 128) col[t] = __ldg(kb + t);
        __syncthreads();
        float a0 = 0.f, a1 = 0.f;
        #pragma unroll 8
        for (int j = 0; j < 32; j += 2){
            a0 = fmaf(__ldg(qw + (kbase+j+0)*C + ic), col[kbase+j+0], a0);
            a1 = fmaf(__ldg(qw + (kbase+j+1)*C + ic), col[kbase+j+1], a1);
        }
        part[ks][ic] = a0 + a1;
        __syncthreads();
        if (ks == 0)
            g_v1[ic] = (part[0][ic] + part[1][ic]) + (part[2][ic] + part[3][ic]);
    } else {
        if (t < 128) col[t] = __ldg(qb + t);
        __syncthreads();
        float a0 = 0.f, a1 = 0.f;
        #pragma unroll 8
        for (int j = 0; j < 32; j += 2){
            a0 = fmaf(col[kbase+j+0], __ldg(kw + (kbase+j+0)*C + ic), a0);
            a1 = fmaf(col[kbase+j+1], __ldg(kw + (kbase+j+1)*C + ic), a1);
        }
        part[ks][ic] = a0 + a1;
        __syncthreads();
        if (ks == 0)
            g_v2[ic] = (part[0][ic] + part[1][ic]) + (part[2][ic] + part[3][ic]);
        if (t < 32){
            float g = 0.f;
            #pragma unroll
            for (int k = t; k < C; k += 32)
                g = fmaf(__ldg(qb + k), __ldg(kb + k), g);
            #pragma unroll
            for (int o = 16; o > 0; o >>= 1)
                g += __shfl_xor_sync(0xFFFFFFFF, g, o);
            if (t == 0) g_gamma[0] = g;
        }
    }
}

// ---------------------------------------------------------------------------
// proj (unchanged — near its HMMA throughput floor)
// ---------------------------------------------------------------------------
#define A_STRIDE 272
#define TILE_BYTES (128 * A_STRIDE)
#define AH_OFF 0
#define AL_OFF (TILE_BYTES)
#define BH_OFF (2*TILE_BYTES)
#define BL_OFF (3*TILE_BYTES)
#define PROJ_SMEM (4*TILE_BYTES)

__global__ __launch_bounds__(512) void proj_kernel(const float* __restrict__ feat){
    extern __shared__ char sm[];
    const uint32_t smb = smem_u32(sm);
    const int tid  = threadIdx.x;
    const int lane = tid & 31;
    const int wid  = tid >> 5;
    const int b    = blockIdx.y;
    const int px0  = blockIdx.x * 128;

    {
        const float4* sh = (const float4*)g_Mhi;
        const float4* sl = (const float4*)g_Mlo;
        for (int e = tid; e < 2048; e += 512){
            int row = e >> 4, seg = e & 15;
            *(float4*)(sm + BH_OFF + row*A_STRIDE + seg*16) = sh[row*16 + seg];
            *(float4*)(sm + BL_OFF + row*A_STRIDE + seg*16) = sl[row*16 + seg];
        }
    }
    {
        const int px  = tid & 127;
        const int ic0 = (tid >> 7) * 32;
        const float* fp = feat + (size_t)(b*C + ic0)*HW + px0 + px;
        char* ah = sm + AH_OFF + px*A_STRIDE + ic0*2;
        char* al = sm + AL_OFF + px*A_STRIDE + ic0*2;
        #pragma unroll
        for (int g = 0; g < 8; g++){
            float v0 = fp[(size_t)(g*4+0)*HW];
            float v1 = fp[(size_t)(g*4+1)*HW];
            float v2 = fp[(size_t)(g*4+2)*HW];
            float v3 = fp[(size_t)(g*4+3)*HW];
            unsigned short h0,h1,h2,h3,l0,l1,l2,l3;
            split_bf16(v0,h0,l0); split_bf16(v1,h1,l1);
            split_bf16(v2,h2,l2); split_bf16(v3,h3,l3);
            *(ull*)(ah + g*8) = (ull)h0 | ((ull)h1<<16) | ((ull)h2<<32) | ((ull)h3<<48);
            *(ull*)(al + g*8) = (ull)l0 | ((ull)l1<<16) | ((ull)l2<<32) | ((ull)l3<<48);
        }
    }
    __syncthreads();

    const int wy = wid >> 1;
    const int wx = wid & 1;
    const int m_base = wy * 16;
    const int n_base = wx * 64;

    float d[8][4];
    #pragma unroll
    for (int j = 0; j < 8; j++)
        #pragma unroll
        for (int k = 0; k < 4; k++) d[j][k] = 0.f;

    const int a_sub = lane >> 3;
    const int a_row_off = (a_sub & 1)*8 + (lane & 7);
    const int a_col_off = (a_sub >> 1)*8;
    const int b_row_off = (a_sub >> 1)*8 + (lane & 7);
    const int b_col_off = (a_sub & 1)*8;

    const uint32_t a_addr_h = smb + AH_OFF + (m_base + a_row_off)*A_STRIDE + a_col_off*2;
    const uint32_t a_addr_l = smb + AL_OFF + (m_base + a_row_off)*A_STRIDE + a_col_off*2;
    const uint32_t b_addr_h = smb + BH_OFF + (n_base + b_row_off)*A_STRIDE + b_col_off*2;
    const uint32_t b_addr_l = smb + BL_OFF + (n_base + b_row_off)*A_STRIDE + b_col_off*2;

    #pragma unroll
    for (int ks = 0; ks < 8; ks++){
        const int k0 = ks * 32;

        uint32_t ah[4], al[4];
        ldm_x4(a_addr_h + k0, ah[0], ah[1], ah[2], ah[3]);
        ldm_x4(a_addr_l + k0, al[0], al[1], al[2], al[3]);

        uint32_t bh[8][2], bl[8][2];
        #pragma unroll
        for (int nb2 = 0; nb2 < 4; nb2++){
            uint32_t r0, r1, r2, r3;
            ldm_x4(b_addr_h + nb2*16*A_STRIDE + k0, r0, r1, r2, r3);
            bh[nb2*2][0] = r0; bh[nb2*2][1] = r1;
            bh[nb2*2+1][0] = r2; bh[nb2*2+1][1] = r3;
            ldm_x4(b_addr_l + nb2*16*A_STRIDE + k0, r0, r1, r2, r3);
            bl[nb2*2][0] = r0; bl[nb2*2][1] = r1;
            bl[nb2*2+1][0] = r2; bl[nb2*2+1][1] = r3;
        }
        #pragma unroll
        for (int nb = 0; nb < 8; nb++){
            mma_bf16(d[nb], ah, bh[nb]);
            mma_bf16(d[nb], ah, bl[nb]);
            mma_bf16(d[nb], al, bh[nb]);
        }
    }

    {
        const int gid = lane >> 2;
        const int tq  = lane & 3;
        float* ub = g_U + (size_t)b*C*HW + px0;
        const int px = m_base + gid;
        #pragma unroll
        for (int nb = 0; nb < 8; nb++){
            const int oc = n_base + nb*8 + tq*2;
            const float v2a = __ldg(g_v2 + oc);
            const float v2b = __ldg(g_v2 + oc + 1);
            float* r0 = ub + (size_t)oc * HW;
            float* r1 = ub + (size_t)(oc+1) * HW;
            r0[px]     = d[nb][0] + v2a;
            r1[px]     = d[nb][1] + v2b;
            r0[px + 8] = d[nb][2] + v2a;
            r1[px + 8] = d[nb][3] + v2b;
        }
    }
}

// ---------------------------------------------------------------------------
// attn v2 (R15 config — measured best) + batched u-prefetch per iteration.
// One CTA per (batch, row). 256 threads = 2 channel-halves x 128 px.
// Static 32KB smem (high occupancy). OOB score exactly 0; softmax; flow gather.
// ---------------------------------------------------------------------------
#define SKS 136

__global__ __launch_bounds__(256) void attn_kernel(const float* __restrict__ feat,
                                                   const float* __restrict__ flow,
                                                   float* __restrict__ out){
    __shared__ float sK[16][3][SKS];
    __shared__ float sV1[C];
    __shared__ float sRed[128][11];

    const int tid  = threadIdx.x;
    const int lane = tid & 31;
    const int wid  = tid >> 5;
    const int b    = blockIdx.y;
    const int row  = blockIdx.x;
    const int x    = tid & 127;
    const int half = tid >> 7;

    for (int e = tid; e < C; e += 256) sV1[e] = g_v1[e];
    if (tid < 48){
        int c16 = tid / 3, r = tid - c16*3;
        sK[c16][r][3]   = 0.f;
        sK[c16][r][132] = 0.f;
    }

    const float* fb = feat + (size_t)b*C*HW;
    const float* ub = g_U + (size_t)b*C*HW + row*W + x;

    float s[9];
    #pragma unroll
    for (int n = 0; n < 9; n++) s[n] = 0.f;
    float a = 0.f;

    for (int i = 0; i < 8; i++){
        // prefetch this block's u values (8 independent LDGs, L2-resident)
        const int chb = half * 64 + i*8;
        float uv[8];
        #pragma unroll
        for (int cc = 0; cc < 8; cc++)
            uv[cc] = __ldg(ub + (size_t)(chb + cc)*HW);

        __syncthreads();
        // stage 16 channels x 3 rows: warp task = one image row (vectorized)
        #pragma unroll
        for (int t = wid; t < 48; t += 8){
            const int c16 = t / 3;
            const int r   = t - c16*3;
            const int ch  = (c16 < 8) ? (i*8 + c16) : (64 + i*8 + (c16 - 8));
            const int gy  = row - 1 + r;
            float* dst = &sK[c16][r][4];
            if ((unsigned)gy < (unsigned)H)
                *(float4*)(dst + 4*lane) = __ldg((const float4*)(fb + (size_t)ch*HW + gy*W) + lane);
            else
                *(float4*)(dst + 4*lane) = make_float4(0.f, 0.f, 0.f, 0.f);
        }
        __syncthreads();

        const int cb16 = half * 8;
        #pragma unroll
        for (int cc = 0; cc < 8; cc++){
            const float* kr = &sK[cb16 + cc][0][0];
            float center = kr[SKS + 4 + x];
            a = fmaf(sV1[chb + cc], center, a);
            #pragma unroll
            for (int dy = 0; dy < 3; dy++){
                s[dy*3+0] = fmaf(uv[cc], kr[dy*SKS + 3 + x], s[dy*3+0]);
                s[dy*3+1] = fmaf(uv[cc], (dy == 1) ? center : kr[dy*SKS + 4 + x], s[dy*3+1]);
                s[dy*3+2] = fmaf(uv[cc], kr[dy*SKS + 5 + x], s[dy*3+2]);
            }
        }
    }

    // reduce the two channel-halves
    if (half == 1){
        float* rp = sRed[x];
        #pragma unroll
        for (int n = 0; n < 9; n++) rp[n] = s[n];
        rp[9] = a;
    }
    __syncthreads();

    if (half == 0){
        const float* rp = sRed[x];
        #pragma unroll
        for (int n = 0; n < 9; n++) s[n] += rp[n];
        a += rp[9];

        const float alpha = a + g_gamma[0];
        const float INV = 0.08838834764831843f;   // 1/sqrt(128)

        float sc[9];
        #pragma unroll
        for (int dy = 0; dy < 3; dy++)
            #pragma unroll
            for (int dx = 0; dx < 3; dx++){
                int n = dy*3+dx;
                bool inb = ((unsigned)(row+dy-1) < (unsigned)H) &&
                           ((unsigned)(x+dx-1) < (unsigned)W);
                sc[n] = inb ? (s[n] + alpha) * INV : 0.f;
            }

        float m = sc[0];
        #pragma unroll
        for (int n = 1; n < 9; n++) m = fmaxf(m, sc[n]);
        float es[9], sum = 0.f;
        #pragma unroll
        for (int n = 0; n < 9; n++){ es[n] = __expf(sc[n] - m); sum += es[n]; }
        const float isum = 1.f / sum;

        const float* fl0 = flow + (size_t)(b*2)*HW;
        const float* fl1 = fl0 + HW;
        float f0 = 0.f, f1 = 0.f;
        #pragma unroll
        for (int dy = 0; dy < 3; dy++)
            #pragma unroll
            for (int dx = 0; dx < 3; dx++){
                int n = dy*3+dx;
                int gy = row + dy - 1, gx = x + dx - 1;
                if ((unsigned)gy < (unsigned)H && (unsigned)gx < (unsigned)W){
                    int pn = gy*W + gx;
                    float pr = es[n] * isum;
                    f0 = fmaf(pr, fl0[pn], f0);
                    f1 = fmaf(pr, fl1[pn], f1);
                }
            }
        out[(size_t)(b*2)*HW + row*W + x]   = f0;
        out[(size_t)(b*2+1)*HW + row*W + x] = f1;
    }
}

extern "C" void kernel_launch(void* const* d_in, const int* in_sizes, int n_in,
                              void* d_out, int out_size){
    const float* feature0 = (const float*)d_in[0];
    const float* flow     = (const float*)d_in[1];
    const float* q_w      = (const float*)d_in[2];
    const float* q_b      = (const float*)d_in[3];
    const float* k_w      = (const float*)d_in[4];
    const float* k_b      = (const float*)d_in[5];
    float* out = (float*)d_out;
    (void)in_sizes; (void)n_in; (void)out_size;

    precomp_kernel<<<130, 512>>>(q_w, q_b, k_w, k_b);

    cudaFuncSetAttribute(proj_kernel, cudaFuncAttributeMaxDynamicSharedMemorySize, PROJ_SMEM);
    proj_kernel<<<dim3(HW/128, BB), 512, PROJ_SMEM>>>(feature0);

    attn_kernel<<<dim3(H, BB), 256>>>(feature0, flow, out);
}